// round 15
// baseline (speedup 1.0000x reference)
#include <cuda_runtime.h>
#include <cuda_bf16.h>
#include <cstdint>

// PathRaster2d R15: halve the thread count. 2048 blocks x 256 threads; each
// block owns one canvas row (y = blockIdx.x); each thread stores 8
// consecutive floats with ONE st.global.v8.f32 zero issued first (no input
// dependency). Reject via control-point bbox (convex hull: all samples lie
// in the cp bbox; margin 2.5 > LINE_WIDTH covers fp rounding, only ever
// keeps extra work): y-test is block-uniform, x-test one compare per thread.
// Active threads (rare) run the proven per-lane sample + exact per-sample
// box prune + full 32-sample min, per-pixel ops bit-identical to all
// passing rounds (rel_err 0.0).

#define CANVAS_H 2048
#define CANVAS_W 2048

__device__ __forceinline__ void stg256(float* p, const float* v)
{
    asm volatile("st.global.v8.f32 [%0], {%1,%2,%3,%4,%5,%6,%7,%8};"
                 :: "l"(p), "f"(v[0]), "f"(v[1]), "f"(v[2]), "f"(v[3]),
                    "f"(v[4]), "f"(v[5]), "f"(v[6]), "f"(v[7])
                 : "memory");
}

__global__ void __launch_bounds__(256)
path_raster_kernel(const float* __restrict__ kp, float* __restrict__ out)
{
    const int tid = threadIdx.x;          // 0..255
    const int tx  = tid & 31;             // lane == sample index
    const int y   = blockIdx.x;           // one row per block
    const int x   = tid * 8;              // 8 consecutive floats per thread

    float* base = out + (size_t)y * CANVAS_W + x;

    // ---- phase 1: one unconditional 256-bit zero store, no input dep ----
    {
        const float z[8] = {0.f, 0.f, 0.f, 0.f, 0.f, 0.f, 0.f, 0.f};
        stg256(base, z);
    }

    // ---- phase 2: exact reject via control-point bbox (hull property) ----
    float4 k03 = __ldg((const float4*)kp);        // y0n x0n y1n x1n
    float2 k45 = __ldg((const float2*)(kp + 4));  // y2n x2n
    float ky0 = __fmul_rn(k03.x, 2048.0f), kx0 = __fmul_rn(k03.y, 2048.0f);
    float ky1 = __fmul_rn(k03.z, 2048.0f), kx1 = __fmul_rn(k03.w, 2048.0f);
    float ky2 = __fmul_rn(k45.x, 2048.0f), kx2 = __fmul_rn(k45.y, 2048.0f);

    float fy = (float)y;
    float ymin = fminf(fminf(ky0, ky1), ky2) - 2.5f;
    float ymax = fmaxf(fmaxf(ky0, ky1), ky2) + 2.5f;
    if (fy < ymin || fy > ymax) return;   // block-uniform exit for most rows

    float xmin = fminf(fminf(kx0, kx1), kx2) - 2.5f;
    float xmax = fmaxf(fmaxf(kx0, kx1), kx2) + 2.5f;
    // warp covers x in [warp_x0, warp_x0+255] (keep warps together for shfl)
    float wx0 = (float)((tid & ~31) * 8);
    float wx1 = wx0 + 255.0f;
    if (wx1 < xmin || wx0 > xmax) return; // warp-uniform exit

    // ---- phase 3: per-lane sample (ref-matched rounding), exact prune ----
    // t_i = i * fl(1/31), endpoint forced to 1.0 (matches jnp.linspace)
    float t = (tx == 31) ? 1.0f : (float)tx * (1.0f / 31.0f);
    float u = __fsub_rn(1.0f, t);
    float b0 = __fmul_rn(u, u);
    float b1 = __fmul_rn(__fmul_rn(2.0f, t), u);
    float b2 = __fmul_rn(t, t);
    float py = __fadd_rn(__fadd_rn(__fmul_rn(b0, ky0), __fmul_rn(b1, ky1)),
                         __fmul_rn(b2, ky2));
    float px = __fadd_rn(__fadd_rn(__fmul_rn(b0, kx0), __fmul_rn(b1, kx1)),
                         __fmul_rn(b2, kx2));

    // Exact point-to-warp-strip distance (strip = 1 row x 256 px); squared
    // threshold 4.5 (> 4.0) pads for rounding — only ever KEEPS samples
    // (dist(pixel,s) >= stripdist(s)).
    float bdy = fabsf(__fsub_rn(fy, py));
    float bdx = fmaxf(fmaxf(wx0 - px, px - wx1), 0.0f);
    bool near = (bdy * bdy + bdx * bdx) < 4.5f;
    unsigned mask = __ballot_sync(0xffffffffu, near);

    if (mask == 0u) return;

    // ---- phase 4 (rare): full min for this thread's 8 pixels, overwrite ----
    const float maxd = sqrtf(2048.0f * 2048.0f + 2048.0f * 2048.0f);
    float fx[8];
    #pragma unroll
    for (int i = 0; i < 8; i++) fx[i] = (float)(x + i);
    float m[8];
    #pragma unroll
    for (int i = 0; i < 8; i++) m[i] = 3.4e38f;
    unsigned mm = mask;                   // warp-uniform loop
    while (mm) {
        int lane = __ffs(mm) - 1;
        mm &= mm - 1u;
        float syv = __shfl_sync(0xffffffffu, py, lane);
        float sxv = __shfl_sync(0xffffffffu, px, lane);
        float dy  = __fsub_rn(fy, syv);
        float dy2 = __fmul_rn(dy, dy);    // separate op, matches reference
        #pragma unroll
        for (int i = 0; i < 8; i++) {
            float d = __fsub_rn(fx[i], sxv);
            m[i] = fminf(m[i], __fadd_rn(dy2, __fmul_rn(d, d)));
        }
    }
    // sqrt BEFORE compare (boundary rounding identical to reference)
    float v[8];
    #pragma unroll
    for (int i = 0; i < 8; i++) {
        float d = sqrtf(m[i]);
        v[i] = (d < 2.0f) ? __fsub_rn(1.0f, __fdiv_rn(d, maxd)) : 0.0f;
    }
    stg256(base, v);
}

extern "C" void kernel_launch(void* const* d_in, const int* in_sizes, int n_in,
                              void* d_out, int out_size)
{
    const float* kp = (const float*)d_in[0];   // [3,2] normalized (y,x)
    float* out = (float*)d_out;                // [2048,2048] fp32

    path_raster_kernel<<<CANVAS_H, 256>>>(kp, out);  // one block per row
}